// round 1
// baseline (speedup 1.0000x reference)
#include <cuda_runtime.h>

// ---------------------------------------------------------------------------
// G1_sub2_and_sub3_update
//
// Stage A (sub2): out[rc[c]] = emb[rc[c]] + sum_{edges e with col==c} emb[ls[s2row[e]]]
//                              + (n_ent - deg2[c])
// Stage B (sub3): msg[c] = sum_{edges e with col==c} out[lc[s3row[e]]]  (updated type rows)
//                 out[rs[c]] = emb[rs[c]] * (1 - (msg[c] + (n_typ - deg3[c])) / (1 + deg3[c]))
//
// Edge lists are sorted by column -> segment bounds via binary search.
// No scratch memory, no atomics. Embedding dim fixed at 128.
// ---------------------------------------------------------------------------

#define EMB_D 128

static __device__ __forceinline__ int lower_bound_i(const int* __restrict__ a, int n, int v) {
    int lo = 0, hi = n;
    while (lo < hi) {
        int m = (lo + hi) >> 1;
        if (__ldg(a + m) < v) lo = m + 1; else hi = m;
    }
    return lo;
}

// One block (128 threads) per type node; thread d owns dimension d.
__global__ void k_type_update(const float* __restrict__ emb,
                              const int* __restrict__ s2row,
                              const int* __restrict__ s2col, int E2,
                              const int* __restrict__ ls,
                              const int* __restrict__ rc,
                              float n_ent_f,
                              float* __restrict__ out) {
    const int c = blockIdx.x;
    const int d = threadIdx.x;   // 0..127

    const int lo = lower_bound_i(s2col, E2, c);
    const int hi = lower_bound_i(s2col, E2, c + 1);

    float acc = 0.f;
    for (int e = lo; e < hi; ++e) {
        const int r   = __ldg(s2row + e);      // uniform across block -> broadcast
        const int src = __ldg(ls + r);
        acc += __ldg(emb + (size_t)src * EMB_D + d);
    }
    const int node = __ldg(rc + c);
    const float base = __ldg(emb + (size_t)node * EMB_D + d);
    out[(size_t)node * EMB_D + d] = base + acc + (n_ent_f - (float)(hi - lo));
}

// One warp per entity node; lane owns 4 dims (float4).
__global__ void k_entity_update(const float* __restrict__ emb,
                                const int* __restrict__ s3row,
                                const int* __restrict__ s3col, int E3,
                                const int* __restrict__ lc,
                                const int* __restrict__ rs,
                                int n_ent, float n_typ_f,
                                float* out) {
    const int wid  = (int)((blockIdx.x * (unsigned)blockDim.x + threadIdx.x) >> 5);
    const int lane = threadIdx.x & 31;
    if (wid >= n_ent) return;
    const int c = wid;

    const int lo = lower_bound_i(s3col, E3, c);
    const int hi = lower_bound_i(s3col, E3, c + 1);
    const float deg = (float)(hi - lo);
    const float inv = 1.f / (1.f + deg);
    const float bias = n_typ_f - deg;

    float4 msg = make_float4(0.f, 0.f, 0.f, 0.f);
    for (int e = lo; e < hi; ++e) {
        const int r = __ldg(s3row + e);        // uniform across warp
        const int t = __ldg(lc + r);           // type node id (row sub2 wrote)
        const float4 v = *((const float4*)(out + (size_t)t * EMB_D) + lane);
        msg.x += v.x; msg.y += v.y; msg.z += v.z; msg.w += v.w;
    }
    msg.x += bias; msg.y += bias; msg.z += bias; msg.w += bias;

    const int node = __ldg(rs + c);
    const float4 e4 = __ldg((const float4*)(emb + (size_t)node * EMB_D) + lane);
    float4 res;
    res.x = e4.x * (1.f - msg.x * inv);
    res.y = e4.y * (1.f - msg.y * inv);
    res.z = e4.z * (1.f - msg.z * inv);
    res.w = e4.w * (1.f - msg.w * inv);
    *((float4*)(out + (size_t)node * EMB_D) + lane) = res;
}

extern "C" void kernel_launch(void* const* d_in, const int* in_sizes, int n_in,
                              void* d_out, int out_size) {
    const float* emb  = (const float*)d_in[0];
    const int* s2row  = (const int*)d_in[1];
    const int* s2col  = (const int*)d_in[2];
    const int* s3row  = (const int*)d_in[3];
    const int* s3col  = (const int*)d_in[4];
    const int* ls     = (const int*)d_in[5];
    const int* rc     = (const int*)d_in[6];
    const int* lc     = (const int*)d_in[7];
    const int* rs     = (const int*)d_in[8];

    const int E2    = in_sizes[1];
    const int E3    = in_sizes[3];
    const int n_ent = in_sizes[5];
    const int n_typ = in_sizes[6];

    float* out = (float*)d_out;

    // Stage A: update the type rows into out.
    k_type_update<<<n_typ, EMB_D>>>(emb, s2row, s2col, E2, ls, rc,
                                    (float)n_ent, out);

    // Stage B: one warp per entity node, gathers updated type rows from out.
    const int threads = 256;                       // 8 warps/CTA
    const int warps_per_cta = threads / 32;
    const int blocks = (n_ent + warps_per_cta - 1) / warps_per_cta;
    k_entity_update<<<blocks, threads>>>(emb, s3row, s3col, E3, lc, rs,
                                         n_ent, (float)n_typ, out);
}

// round 2
// speedup vs baseline: 1.8888x; 1.8888x over previous
#include <cuda_runtime.h>

// ---------------------------------------------------------------------------
// G1_sub2_and_sub3_update
//
// Stage A (sub2): out[rc[c]] = emb[rc[c]] + sum_{e: col==c} emb[ls[s2row[e]]]
//                              + (n_ent - deg2[c])
// Stage B (sub3): msg[c] = sum_{e: col==c} out[lc[s3row[e]]]   (updated type rows)
//                 out[rs[c]] = emb[rs[c]] * (1 - (msg[c] + (n_typ - deg3[c])) / (1 + deg3[c]))
//
// Edge lists are sorted by column. Segments are (in practice) uniform-degree:
// guess bounds as [c*deg, (c+1)*deg), validate with O(1) loads, fall back to
// binary search only if the guess is wrong. No atomics, no scratch memory.
// ---------------------------------------------------------------------------

#define EMB_D 128

static __device__ __forceinline__ int lower_bound_i(const int* __restrict__ a, int n, int v) {
    int lo = 0, hi = n;
    while (lo < hi) {
        int m = (lo + hi) >> 1;
        if (__ldg(a + m) < v) lo = m + 1; else hi = m;
    }
    return lo;
}

// Find [lo,hi) for segment c in sorted col array of length E.
// degGuess = E / ncols (uniform-degree fast path).
static __device__ __forceinline__ void seg_bounds(const int* __restrict__ col, int E,
                                                  int c, int degGuess,
                                                  int& lo, int& hi) {
    lo = c * degGuess;
    hi = lo + degGuess;
    bool ok = (hi <= E)
           && (__ldg(col + lo) == c)
           && (__ldg(col + hi - 1) == c)
           && (lo == 0 || __ldg(col + lo - 1) != c)
           && (hi == E || __ldg(col + hi) != c);
    if (!ok) {                      // cold path: exact binary search
        lo = lower_bound_i(col, E, c);
        hi = lower_bound_i(col, E, c + 1);
    }
}

// ---------------- Stage A: one block (128 threads) per type node ----------
__global__ void k_type_update(const float* __restrict__ emb,
                              const int* __restrict__ s2row,
                              const int* __restrict__ s2col, int E2, int degGuess2,
                              const int* __restrict__ ls,
                              const int* __restrict__ rc,
                              float n_ent_f,
                              float* __restrict__ out) {
    const int c = blockIdx.x;
    const int d = threadIdx.x;   // 0..127

    int lo, hi;
    seg_bounds(s2col, E2, c, degGuess2, lo, hi);
    const int deg = hi - lo;

    float acc = 0.f;
    int e = lo;
    // Unroll-by-4: batch the index loads so the row gathers overlap.
    for (; e + 4 <= hi; e += 4) {
        int r0 = __ldg(s2row + e + 0);
        int r1 = __ldg(s2row + e + 1);
        int r2 = __ldg(s2row + e + 2);
        int r3 = __ldg(s2row + e + 3);
        int s0 = __ldg(ls + r0);
        int s1 = __ldg(ls + r1);
        int s2 = __ldg(ls + r2);
        int s3 = __ldg(ls + r3);
        float v0 = __ldg(emb + (size_t)s0 * EMB_D + d);
        float v1 = __ldg(emb + (size_t)s1 * EMB_D + d);
        float v2 = __ldg(emb + (size_t)s2 * EMB_D + d);
        float v3 = __ldg(emb + (size_t)s3 * EMB_D + d);
        acc += (v0 + v1) + (v2 + v3);
    }
    for (; e < hi; ++e) {
        int r = __ldg(s2row + e);
        int s = __ldg(ls + r);
        acc += __ldg(emb + (size_t)s * EMB_D + d);
    }

    const int node = __ldg(rc + c);
    const float base = __ldg(emb + (size_t)node * EMB_D + d);
    out[(size_t)node * EMB_D + d] = base + acc + (n_ent_f - (float)deg);
}

// ---------------- Stage B: one warp per entity node -----------------------
__global__ void k_entity_update(const float* __restrict__ emb,
                                const int* __restrict__ s3row,
                                const int* __restrict__ s3col, int E3, int degGuess3,
                                const int* __restrict__ lc,
                                const int* __restrict__ rs,
                                int n_ent, float n_typ_f,
                                float* out) {
    const int c    = (int)((blockIdx.x * (unsigned)blockDim.x + threadIdx.x) >> 5);
    const int lane = threadIdx.x & 31;
    if (c >= n_ent) return;

    int lo, hi;
    seg_bounds(s3col, E3, c, degGuess3, lo, hi);
    const int deg = hi - lo;

    const float inv  = 1.f / (1.f + (float)deg);
    const float bias = n_typ_f - (float)deg;

    const int node = __ldg(rs + c);
    // Entity row load kicked off early; independent of the gathers below.
    const float4 e4 = __ldg((const float4*)(emb + (size_t)node * EMB_D) + lane);

    float4 msg = make_float4(bias, bias, bias, bias);
    if (deg == 4) {                         // hot path: all 4 gathers in flight
        int r0 = __ldg(s3row + lo + 0);
        int r1 = __ldg(s3row + lo + 1);
        int r2 = __ldg(s3row + lo + 2);
        int r3 = __ldg(s3row + lo + 3);
        int t0 = __ldg(lc + r0);
        int t1 = __ldg(lc + r1);
        int t2 = __ldg(lc + r2);
        int t3 = __ldg(lc + r3);
        float4 v0 = *((const float4*)(out + (size_t)t0 * EMB_D) + lane);
        float4 v1 = *((const float4*)(out + (size_t)t1 * EMB_D) + lane);
        float4 v2 = *((const float4*)(out + (size_t)t2 * EMB_D) + lane);
        float4 v3 = *((const float4*)(out + (size_t)t3 * EMB_D) + lane);
        msg.x += (v0.x + v1.x) + (v2.x + v3.x);
        msg.y += (v0.y + v1.y) + (v2.y + v3.y);
        msg.z += (v0.z + v1.z) + (v2.z + v3.z);
        msg.w += (v0.w + v1.w) + (v2.w + v3.w);
    } else {
        for (int e = lo; e < hi; ++e) {
            int r = __ldg(s3row + e);
            int t = __ldg(lc + r);
            float4 v = *((const float4*)(out + (size_t)t * EMB_D) + lane);
            msg.x += v.x; msg.y += v.y; msg.z += v.z; msg.w += v.w;
        }
    }

    float4 res;
    res.x = e4.x * (1.f - msg.x * inv);
    res.y = e4.y * (1.f - msg.y * inv);
    res.z = e4.z * (1.f - msg.z * inv);
    res.w = e4.w * (1.f - msg.w * inv);
    *((float4*)(out + (size_t)node * EMB_D) + lane) = res;
}

extern "C" void kernel_launch(void* const* d_in, const int* in_sizes, int n_in,
                              void* d_out, int out_size) {
    const float* emb  = (const float*)d_in[0];
    const int* s2row  = (const int*)d_in[1];
    const int* s2col  = (const int*)d_in[2];
    const int* s3row  = (const int*)d_in[3];
    const int* s3col  = (const int*)d_in[4];
    const int* ls     = (const int*)d_in[5];
    const int* rc     = (const int*)d_in[6];
    const int* lc     = (const int*)d_in[7];
    const int* rs     = (const int*)d_in[8];

    const int E2    = in_sizes[1];
    const int E3    = in_sizes[3];
    const int n_ent = in_sizes[5];
    const int n_typ = in_sizes[6];

    const int degGuess2 = (n_typ > 0) ? (E2 / n_typ) : 1;
    const int degGuess3 = (n_ent > 0) ? (E3 / n_ent) : 1;

    float* out = (float*)d_out;

    // Stage A: update the type rows into out.
    k_type_update<<<n_typ, EMB_D>>>(emb, s2row, s2col, E2, degGuess2, ls, rc,
                                    (float)n_ent, out);

    // Stage B: one warp per entity node, gathers updated type rows from out.
    const int threads = 256;                       // 8 warps/CTA
    const int warps_per_cta = threads / 32;
    const int blocks = (n_ent + warps_per_cta - 1) / warps_per_cta;
    k_entity_update<<<blocks, threads>>>(emb, s3row, s3col, E3, degGuess3, lc, rs,
                                         n_ent, (float)n_typ, out);
}